// round 2
// baseline (speedup 1.0000x reference)
#include <cuda_runtime.h>
#include <math.h>

#define B_   8192
#define N_   4096
#define H_   256
#define NM_  2048
#define NLAY_ 8

// ---------------------------------------------------------------------------
// Scratch (static device globals — no allocation anywhere)
// ---------------------------------------------------------------------------
__device__ float g_h1[(size_t)B_ * H_];          //  8 MB
__device__ float g_h2[(size_t)B_ * H_];          //  8 MB
__device__ float g_st[(size_t)B_ * N_];          // 128 MB

// ---------------------------------------------------------------------------
// Checkerboard index math.
// Flattened 64x64 grid, cb(k) = ((k/64) + (k%64)) % 2.
// For layer parity p: masked (input) set im has cb==p, updated set iu has cb!=p.
// c-th element of each set (c in [0,2048)):
//   grid row g = c>>5, within-row m = c&31
//   im: col j = 2*m + ((p + g) & 1)
//   iu: col j = 2*m + ((p + g + 1) & 1)
// ---------------------------------------------------------------------------
__device__ __forceinline__ int gather_im(int c, int p) {
    int g = c >> 5, m = c & 31;
    return g * 64 + 2 * m + ((p + g) & 1);
}
__device__ __forceinline__ int gather_iu(int c, int p) {
    int g = c >> 5, m = c & 31;
    return g * 64 + 2 * m + ((p + g + 1) & 1);
}

// ---------------------------------------------------------------------------
// Init: x = z, logdet = 0
// ---------------------------------------------------------------------------
__global__ void init_kernel(const float* __restrict__ z, float* __restrict__ x,
                            float* __restrict__ logdet) {
    size_t i = (size_t)blockIdx.x * blockDim.x + threadIdx.x;
    size_t total = (size_t)B_ * N_;
    size_t stride = (size_t)gridDim.x * blockDim.x;
    for (size_t k = i; k < total; k += stride) x[k] = z[k];
    if (i < B_) logdet[i] = 0.0f;
}

// ---------------------------------------------------------------------------
// Tiled SGEMM:  C[M x NCOLS] = act( A[M x K_] * W[K_ x NCOLS] + bias )
//   BM=BN=128, BK=16, 256 threads, 8x8 microtile per thread.
//   ASRC: 0 = gather from x (lda = N_, checkerboard im), 1 = g_h1, 2 = g_h2
//   CDST: 0 = g_h1, 1 = g_h2, 2 = g_st
//   ACT : 1 = leaky_relu(0.2), 0 = none
//   M is always 8192; M, NCOLS, K_ all divisible by tile dims -> no bounds checks.
// ---------------------------------------------------------------------------
template <int K_, int NCOLS, int ASRC, int CDST, int ACT>
__global__ void __launch_bounds__(256)
gemm_kernel(const float* __restrict__ x, const float* __restrict__ W,
            const float* __restrict__ bias, int parity) {
    constexpr int BM = 128, BN = 128, BK = 16, TM = 8, TN = 8;

    __shared__ float As[BK][BM + 1];           // +1 pad: avoid write conflicts
    __shared__ __align__(16) float Bs[BK][BN];

    const int tid  = threadIdx.x;
    const int row0 = blockIdx.y * BM;
    const int col0 = blockIdx.x * BN;

    const float* A;
    int lda;
    if (ASRC == 0)      { A = x;    lda = N_; }
    else if (ASRC == 1) { A = g_h1; lda = H_; }
    else                { A = g_h2; lda = H_; }

    const int tRow = (tid / 16) * TM;   // 0..120
    const int tCol = (tid % 16) * TN;   // 0..120

    // A-loader: each thread loads one (row, k) per pass, 8 passes over rows
    const int aRow = tid / BK;          // 0..15
    const int aK   = tid % BK;          // 0..15
    // B-loader: each thread loads 8 contiguous cols of one k-row
    const int bRow = tid / 16;          // 0..15 (k within tile)
    const int bCol = (tid % 16) * 8;    // 0..120

    float acc[TM][TN];
#pragma unroll
    for (int i = 0; i < TM; i++)
#pragma unroll
        for (int j = 0; j < TN; j++) acc[i][j] = 0.0f;

    for (int kt = 0; kt < K_; kt += BK) {
        // ---- load A tile (BM x BK), stored transposed As[k][row] ----
#pragma unroll
        for (int i = 0; i < BM; i += 16) {
            int r = row0 + aRow + i;
            int k = kt + aK;
            int kk;
            if (ASRC == 0) kk = gather_im(k, parity);
            else           kk = k;
            As[aK][aRow + i] = A[(size_t)r * lda + kk];
        }
        // ---- load B tile (BK x BN), vectorized float4 ----
        {
            const float4* Bp = reinterpret_cast<const float4*>(
                &W[(size_t)(kt + bRow) * NCOLS + col0 + bCol]);
            float4 v0 = Bp[0];
            float4 v1 = Bp[1];
            *reinterpret_cast<float4*>(&Bs[bRow][bCol])     = v0;
            *reinterpret_cast<float4*>(&Bs[bRow][bCol + 4]) = v1;
        }
        __syncthreads();

        // ---- compute ----
#pragma unroll
        for (int k = 0; k < BK; k++) {
            float ra[TM], rb[TN];
#pragma unroll
            for (int i = 0; i < TM; i++) ra[i] = As[k][tRow + i];
#pragma unroll
            for (int j = 0; j < TN; j++) rb[j] = Bs[k][tCol + j];
#pragma unroll
            for (int i = 0; i < TM; i++)
#pragma unroll
                for (int j = 0; j < TN; j++) acc[i][j] += ra[i] * rb[j];
        }
        __syncthreads();
    }

    // ---- epilogue: bias + activation, write to CDST ----
    float* Cout = (CDST == 0) ? g_h1 : (CDST == 1) ? g_h2 : g_st;
#pragma unroll
    for (int i = 0; i < TM; i++) {
        int r = row0 + tRow + i;
#pragma unroll
        for (int j = 0; j < TN; j++) {
            int c = col0 + tCol + j;
            float v = acc[i][j] + bias[c];
            if (ACT) v = (v > 0.0f) ? v : 0.2f * v;
            Cout[(size_t)r * NCOLS + c] = v;
        }
    }
}

// ---------------------------------------------------------------------------
// Update: s = 2*tanh(st[:, :2048]); t = st[:, 2048:]
//         x[:, iu] = x[:, iu] * exp(s) + t ;  logdet += sum(s)
// One CTA per row, 256 threads, 8 columns each.
// ---------------------------------------------------------------------------
__global__ void __launch_bounds__(256)
update_kernel(float* __restrict__ x, float* __restrict__ logdet, int parity) {
    const int r   = blockIdx.x;
    const int tid = threadIdx.x;
    const float* strow = &g_st[(size_t)r * N_];
    float* xrow = &x[(size_t)r * N_];

    float acc = 0.0f;
#pragma unroll
    for (int u = 0; u < NM_ / 256; u++) {
        int c = tid + u * 256;
        float s = 2.0f * tanhf(strow[c]);
        float t = strow[NM_ + c];
        int col = gather_iu(c, parity);
        float xv = xrow[col];
        xrow[col] = xv * expf(s) + t;
        acc += s;
    }

    __shared__ float red[256];
    red[tid] = acc;
    __syncthreads();
#pragma unroll
    for (int sft = 128; sft > 0; sft >>= 1) {
        if (tid < sft) red[tid] += red[tid + sft];
        __syncthreads();
    }
    if (tid == 0) logdet[r] += red[0];
}

// ---------------------------------------------------------------------------
// Launch
// ---------------------------------------------------------------------------
extern "C" void kernel_launch(void* const* d_in, const int* in_sizes, int n_in,
                              void* d_out, int out_size) {
    const float* z  = (const float*)d_in[0];
    const float* W1 = (const float*)d_in[1];
    const float* b1 = (const float*)d_in[2];
    const float* W2 = (const float*)d_in[3];
    const float* b2 = (const float*)d_in[4];
    const float* W3 = (const float*)d_in[5];
    const float* b3 = (const float*)d_in[6];

    float* x      = (float*)d_out;                 // B_*N_ floats
    float* logdet = x + (size_t)B_ * N_;           // B_ floats

    init_kernel<<<1024, 256>>>(z, x, logdet);

    for (int i = 0; i < NLAY_; i++) {
        const int p = i & 1;
        const float* w1 = W1 + (size_t)i * NM_ * H_;
        const float* w2 = W2 + (size_t)i * H_ * H_;
        const float* w3 = W3 + (size_t)i * H_ * N_;
        const float* bb1 = b1 + (size_t)i * H_;
        const float* bb2 = b2 + (size_t)i * H_;
        const float* bb3 = b3 + (size_t)i * N_;

        // h1 = leaky( x[:, im] @ W1 + b1 )      (8192x2048)x(2048x256)
        gemm_kernel<NM_, H_, 0, 0, 1><<<dim3(H_ / 128, B_ / 128), 256>>>(x, w1, bb1, p);
        // h2 = leaky( h1 @ W2 + b2 )            (8192x256)x(256x256)
        gemm_kernel<H_, H_, 1, 1, 1><<<dim3(H_ / 128, B_ / 128), 256>>>(x, w2, bb2, p);
        // st = h2 @ W3 + b3                     (8192x256)x(256x4096)
        gemm_kernel<H_, N_, 2, 2, 0><<<dim3(N_ / 128, B_ / 128), 256>>>(x, w3, bb3, p);
        // affine update + logdet
        update_kernel<<<B_, 256>>>(x, logdet, p);
    }
}